// round 3
// baseline (speedup 1.0000x reference)
#include <cuda_runtime.h>

#define FCH 32    // node feature channels
#define SCH 16    // edge feature channels
#define SG  17    // s-groups incl. bias slot
#define ZW  (SG*FCH)   // 544
#define N_MAX 50048

// Scratch (device globals; no allocation allowed)
__device__ float d_Z[(size_t)N_MAX * ZW];      // ~109 MB: per-node expanded features
__device__ float d_h[(size_t)N_MAX * FCH];     // layer-1 output
__device__ float d_agg[(size_t)N_MAX * FCH];   // scatter accumulator
__device__ float d_pooled[FCH];

// ---------------------------------------------------------------------------
// K1: Z[n, s, o] = sum_f h[n,f] * Wext[f, s*32+o]
//     Wext[f, s*32+o] = fgn_w[s, f*32+o] for s<16,  fgn_b[f*32+o] for s==16.
//     Also zeroes the agg row for n (and pooled, once).
// ---------------------------------------------------------------------------
__global__ __launch_bounds__(256) void k_expand(
    const float* __restrict__ h_ext, const float* __restrict__ fgn_w,
    const float* __restrict__ fgn_b, int N, int zero_pooled, int use_dh)
{
    extern __shared__ float sW[];  // FCH*ZW floats = 69632 B
    for (int i = threadIdx.x; i < FCH * ZW; i += blockDim.x) {
        int k = i / ZW;
        int j = i - k * ZW;
        int s = j >> 5, o = j & 31;
        sW[i] = (s < SCH) ? fgn_w[s * (FCH * FCH) + k * FCH + o]
                          : fgn_b[k * FCH + o];
    }
    if (zero_pooled && blockIdx.x == 0 && threadIdx.x < FCH)
        d_pooled[threadIdx.x] = 0.0f;
    __syncthreads();

    const float* h = use_dh ? d_h : h_ext;
    const float4* sW4 = (const float4*)sW;

    for (int n = blockIdx.x * blockDim.x + threadIdx.x; n < N;
         n += gridDim.x * blockDim.x) {
        float xr[FCH];
        const float4* hp = (const float4*)(h + (size_t)n * FCH);
        #pragma unroll
        for (int i = 0; i < FCH / 4; i++) {
            float4 v = hp[i];
            xr[4*i+0] = v.x; xr[4*i+1] = v.y; xr[4*i+2] = v.z; xr[4*i+3] = v.w;
        }
        float4* zp = (float4*)(d_Z + (size_t)n * ZW);
        #pragma unroll 2
        for (int j4 = 0; j4 < ZW / 4; j4++) {
            float4 acc = make_float4(0.f, 0.f, 0.f, 0.f);
            #pragma unroll
            for (int k = 0; k < FCH; k++) {
                float4 w = sW4[k * (ZW / 4) + j4];   // uniform -> smem broadcast
                acc.x = fmaf(xr[k], w.x, acc.x);
                acc.y = fmaf(xr[k], w.y, acc.y);
                acc.z = fmaf(xr[k], w.z, acc.z);
                acc.w = fmaf(xr[k], w.w, acc.w);
            }
            zp[j4] = acc;
        }
        // zero agg row for this node (consumed by k_edge atomics)
        float4 zv = make_float4(0.f, 0.f, 0.f, 0.f);
        float4* ap = (float4*)(d_agg + (size_t)n * FCH);
        #pragma unroll
        for (int i = 0; i < FCH / 4; i++) ap[i] = zv;
    }
}

// ---------------------------------------------------------------------------
// K2: per edge: msg[o] = sum_{s<16} e[e,s]*Z[src,s,o] + Z[src,16,o]
//     8 lanes per edge (each lane owns 4 consecutive o), 4 edges per warp.
//     Scatter via atomicAdd into d_agg[dst].
// ---------------------------------------------------------------------------
__global__ __launch_bounds__(256) void k_edge(
    const float* __restrict__ ef, const int* __restrict__ src,
    const int* __restrict__ dst, int E)
{
    int lane = threadIdx.x & 31;
    int sub  = lane & 7;    // which float4 of the 32-wide message
    int g    = lane >> 3;   // edge slot within warp (0..3)
    int warpId = (blockIdx.x * blockDim.x + threadIdx.x) >> 5;
    int nWarp  = (gridDim.x * blockDim.x) >> 5;

    for (int base = warpId * 4; base < E; base += nWarp * 4) {
        int edge = base + g;
        bool valid = edge < E;
        float es0 = 0.f, es1 = 0.f;
        int sn = 0, dn = 0;
        if (valid) {
            es0 = ef[(size_t)edge * SCH + sub];
            es1 = ef[(size_t)edge * SCH + 8 + sub];
            sn = src[edge];
            dn = dst[edge];
        }
        const float4* zrow = (const float4*)(d_Z + (size_t)sn * ZW) + sub;
        float4 acc = make_float4(0.f, 0.f, 0.f, 0.f);
        #pragma unroll
        for (int s = 0; s < SG; s++) {
            float c;
            if (s < SCH) {
                float v = (s < 8) ? es0 : es1;
                c = __shfl_sync(0xffffffffu, v, (lane & 24) | (s & 7));
            } else {
                c = 1.0f;   // bias slot
            }
            float4 zv = zrow[s * 8];
            acc.x = fmaf(c, zv.x, acc.x);
            acc.y = fmaf(c, zv.y, acc.y);
            acc.z = fmaf(c, zv.z, acc.z);
            acc.w = fmaf(c, zv.w, acc.w);
        }
        if (valid) {
            float* a = d_agg + (size_t)dn * FCH + sub * 4;
            atomicAdd(a + 0, acc.x);
            atomicAdd(a + 1, acc.y);
            atomicAdd(a + 2, acc.z);
            atomicAdd(a + 3, acc.w);
        }
    }
}

// ---------------------------------------------------------------------------
// K3: hout[n] = relu(agg[n] + h[n] @ root + bias). do_pool: accumulate
//     sum over nodes into d_pooled instead of storing hout.
// ---------------------------------------------------------------------------
__global__ __launch_bounds__(256) void k_node(
    const float* __restrict__ hin_ext, const float* __restrict__ root,
    const float* __restrict__ bias, int N, int use_dh, int do_pool)
{
    __shared__ float sR[FCH * FCH];
    __shared__ float sB[FCH];
    __shared__ float sPool[FCH];
    for (int i = threadIdx.x; i < FCH * FCH; i += blockDim.x) sR[i] = root[i];
    if (threadIdx.x < FCH) { sB[threadIdx.x] = bias[threadIdx.x]; sPool[threadIdx.x] = 0.f; }
    __syncthreads();

    const float* hin = use_dh ? d_h : hin_ext;
    const float4* sR4 = (const float4*)sR;
    const float4* sB4 = (const float4*)sB;
    int lane = threadIdx.x & 31;

    float pacc[FCH];
    #pragma unroll
    for (int i = 0; i < FCH; i++) pacc[i] = 0.f;

    for (int n = blockIdx.x * blockDim.x + threadIdx.x; n < N;
         n += gridDim.x * blockDim.x) {
        float xr[FCH];
        const float4* hp = (const float4*)(hin + (size_t)n * FCH);
        #pragma unroll
        for (int i = 0; i < FCH / 4; i++) {
            float4 v = hp[i];
            xr[4*i+0] = v.x; xr[4*i+1] = v.y; xr[4*i+2] = v.z; xr[4*i+3] = v.w;
        }
        const float4* ag = (const float4*)(d_agg + (size_t)n * FCH);
        float4* op = (float4*)(d_h + (size_t)n * FCH);
        #pragma unroll
        for (int o4 = 0; o4 < FCH / 4; o4++) {
            float4 a = ag[o4];
            float4 b = sB4[o4];
            float4 acc = make_float4(a.x + b.x, a.y + b.y, a.z + b.z, a.w + b.w);
            #pragma unroll
            for (int k = 0; k < FCH; k++) {
                float4 w = sR4[k * (FCH / 4) + o4];
                acc.x = fmaf(xr[k], w.x, acc.x);
                acc.y = fmaf(xr[k], w.y, acc.y);
                acc.z = fmaf(xr[k], w.z, acc.z);
                acc.w = fmaf(xr[k], w.w, acc.w);
            }
            acc.x = fmaxf(acc.x, 0.f);
            acc.y = fmaxf(acc.y, 0.f);
            acc.z = fmaxf(acc.z, 0.f);
            acc.w = fmaxf(acc.w, 0.f);
            if (do_pool) {
                pacc[4*o4+0] += acc.x; pacc[4*o4+1] += acc.y;
                pacc[4*o4+2] += acc.z; pacc[4*o4+3] += acc.w;
            } else {
                op[o4] = acc;
            }
        }
    }

    if (do_pool) {
        // rotated channel order -> 32 lanes hit 32 distinct banks each step
        #pragma unroll
        for (int j = 0; j < FCH; j++) {
            int o = (lane + j) & 31;
            atomicAdd(&sPool[o], pacc[o]);
        }
        __syncthreads();
        if (threadIdx.x < FCH)
            atomicAdd(&d_pooled[threadIdx.x], sPool[threadIdx.x]);
    }
}

// ---------------------------------------------------------------------------
// Final: out[0] = pooled . dense_w + dense_b
// ---------------------------------------------------------------------------
__global__ void k_final(const float* __restrict__ dw, const float* __restrict__ db,
                        float* __restrict__ out)
{
    int l = threadIdx.x;
    float v = (l < FCH) ? d_pooled[l] * dw[l] : 0.f;
    #pragma unroll
    for (int off = 16; off > 0; off >>= 1)
        v += __shfl_down_sync(0xffffffffu, v, off);
    if (l == 0) out[0] = v + db[0];
}

extern "C" void kernel_launch(void* const* d_in, const int* in_sizes, int n_in,
                              void* d_out, int out_size)
{
    const float* x      = (const float*)d_in[0];
    const float* e      = (const float*)d_in[1];
    const int*   src    = (const int*)d_in[2];
    const int*   dst    = (const int*)d_in[3];
    const float* fgn_w1 = (const float*)d_in[4];
    const float* fgn_b1 = (const float*)d_in[5];
    const float* root1  = (const float*)d_in[6];
    const float* bias1  = (const float*)d_in[7];
    const float* fgn_w2 = (const float*)d_in[8];
    const float* fgn_b2 = (const float*)d_in[9];
    const float* root2  = (const float*)d_in[10];
    const float* bias2  = (const float*)d_in[11];
    const float* dw     = (const float*)d_in[12];
    const float* db     = (const float*)d_in[13];

    int N = in_sizes[0] / FCH;
    int E = in_sizes[2];
    if (N > N_MAX) N = N_MAX;  // scratch bound (dataset: N=50000)

    size_t smemW = (size_t)FCH * ZW * sizeof(float);  // 69632 B > 48K default
    cudaFuncSetAttribute(k_expand, cudaFuncAttributeMaxDynamicSharedMemorySize,
                         (int)smemW);

    const int NB = 148 * 3;                 // node-kernel blocks (grid-stride)
    const int EB = (E * 8 + 255) / 256;     // 8 threads per edge

    // Layer 1
    k_expand<<<NB, 256, smemW>>>(x, fgn_w1, fgn_b1, N, /*zero_pooled=*/1, /*use_dh=*/0);
    k_edge<<<EB, 256>>>(e, src, dst, E);
    k_node<<<NB, 256>>>(x, root1, bias1, N, /*use_dh=*/0, /*do_pool=*/0);   // -> d_h

    // Layer 2
    k_expand<<<NB, 256, smemW>>>(x, fgn_w2, fgn_b2, N, 0, /*use_dh=*/1);
    k_edge<<<EB, 256>>>(e, src, dst, E);
    k_node<<<NB, 256>>>(x, root2, bias2, N, /*use_dh=*/1, /*do_pool=*/1);   // -> d_pooled

    k_final<<<1, 32>>>(dw, db, (float*)d_out);
}

// round 4
// speedup vs baseline: 1.2262x; 1.2262x over previous
#include <cuda_runtime.h>

#define FCH 32    // node feature channels
#define SCH 16    // edge feature channels
#define SG  17    // s-groups incl. bias slot
#define ZW  (SG*FCH)   // 544
#define N_MAX 50048

// Scratch (device globals; no allocation allowed)
__device__ float d_Z[(size_t)N_MAX * ZW];      // ~109 MB: per-node expanded features
__device__ float d_h[(size_t)N_MAX * FCH];     // layer-1 output
__device__ float d_agg[(size_t)N_MAX * FCH];   // scatter accumulator
__device__ float d_pooled[FCH];

// ---- packed f32x2 helpers (Blackwell) --------------------------------------
__device__ __forceinline__ unsigned long long pack2(float v) {
    unsigned long long r;
    asm("mov.b64 %0, {%1, %1};" : "=l"(r) : "f"(v));
    return r;
}
__device__ __forceinline__ unsigned long long fma2(
    unsigned long long a, unsigned long long b, unsigned long long c) {
    unsigned long long d;
    asm("fma.rn.f32x2 %0, %1, %2, %3;" : "=l"(d) : "l"(a), "l"(b), "l"(c));
    return d;
}

// ---------------------------------------------------------------------------
// K1: Z[n, s, o] = sum_f h[n,f] * Wext[f, s*32+o]
//     Warp = 8 nodes. lane -> (g = node slot 0..3, sub = o-chunk 0..7).
//     Each lane computes nodes (base+g) and (base+g+4): weight LDS reused x2,
//     math in fma.rn.f32x2 (o-pairs), stores are full 128B lines.
//     Also zeroes the agg rows (and pooled, once).
// ---------------------------------------------------------------------------
__global__ __launch_bounds__(256) void k_expand(
    const float* __restrict__ h_ext, const float* __restrict__ fgn_w,
    const float* __restrict__ fgn_b, int N, int zero_pooled, int use_dh)
{
    extern __shared__ float sW[];  // [FCH][ZW] = 69632 B
    for (int i = threadIdx.x; i < FCH * ZW; i += blockDim.x) {
        int k = i / ZW;
        int j = i - k * ZW;
        int s = j >> 5, o = j & 31;
        sW[i] = (s < SCH) ? fgn_w[s * (FCH * FCH) + k * FCH + o]
                          : fgn_b[k * FCH + o];
    }
    if (zero_pooled && blockIdx.x == 0 && threadIdx.x < FCH)
        d_pooled[threadIdx.x] = 0.0f;
    __syncthreads();

    const float* h = use_dh ? d_h : h_ext;
    const ulonglong2* sWu = (const ulonglong2*)sW;   // 16B units == float4 units

    int lane = threadIdx.x & 31;
    int g    = lane >> 3;   // node slot within warp (0..3)
    int sub  = lane & 7;    // which 16B o-chunk (0..7)
    int warpId = (blockIdx.x * blockDim.x + threadIdx.x) >> 5;
    int nWarp  = (gridDim.x * blockDim.x) >> 5;

    for (int base = warpId * 8; base < N; base += nWarp * 8) {
        int nA = base + g;
        int nB = base + g + 4;
        int rA = nA < N ? nA : N - 1;
        int rB = nB < N ? nB : N - 1;

        // load both x rows into registers (row = 128B = 1 line each)
        float xa[FCH], xb[FCH];
        const float4* pa = (const float4*)(h + (size_t)rA * FCH);
        const float4* pb = (const float4*)(h + (size_t)rB * FCH);
        #pragma unroll
        for (int i = 0; i < FCH / 4; i++) {
            float4 v = pa[i];
            xa[4*i+0] = v.x; xa[4*i+1] = v.y; xa[4*i+2] = v.z; xa[4*i+3] = v.w;
        }
        #pragma unroll
        for (int i = 0; i < FCH / 4; i++) {
            float4 v = pb[i];
            xb[4*i+0] = v.x; xb[4*i+1] = v.y; xb[4*i+2] = v.z; xb[4*i+3] = v.w;
        }

        // zero agg rows (8 lanes with same g cover one node's 8 float4s)
        float4 zv = make_float4(0.f, 0.f, 0.f, 0.f);
        if (nA < N) ((float4*)(d_agg + (size_t)nA * FCH))[sub] = zv;
        if (nB < N) ((float4*)(d_agg + (size_t)nB * FCH))[sub] = zv;

        ulonglong2* zA = (ulonglong2*)(d_Z + (size_t)rA * ZW);
        ulonglong2* zB = (ulonglong2*)(d_Z + (size_t)rB * ZW);

        #pragma unroll 1
        for (int s = 0; s < SG; s++) {
            const ulonglong2* wp = sWu + s * 8 + sub;   // sW[k][s*32 + sub*4 ..]
            unsigned long long a0 = 0, a1 = 0, b0 = 0, b1 = 0;
            #pragma unroll
            for (int k = 0; k < FCH; k++) {
                ulonglong2 w = wp[k * (ZW / 4)];        // one LDS.128, bcast x4 over g
                unsigned long long xA2 = pack2(xa[k]);
                unsigned long long xB2 = pack2(xb[k]);
                a0 = fma2(xA2, w.x, a0);
                a1 = fma2(xA2, w.y, a1);
                b0 = fma2(xB2, w.x, b0);
                b1 = fma2(xB2, w.y, b1);
            }
            ulonglong2 ra; ra.x = a0; ra.y = a1;
            ulonglong2 rb; rb.x = b0; rb.y = b1;
            if (nA < N) zA[s * 8 + sub] = ra;           // full 128B line per (node,s)
            if (nB < N) zB[s * 8 + sub] = rb;
        }
    }
}

// ---------------------------------------------------------------------------
// K2: per edge: msg[o] = sum_{s<16} e[e,s]*Z[src,s,o] + Z[src,16,o]
//     8 lanes per edge (each lane owns 4 consecutive o), 4 edges per warp.
//     Scatter via one red.global.add.v4.f32 per lane.
// ---------------------------------------------------------------------------
__global__ __launch_bounds__(256) void k_edge(
    const float* __restrict__ ef, const int* __restrict__ src,
    const int* __restrict__ dst, int E)
{
    int lane = threadIdx.x & 31;
    int sub  = lane & 7;    // which float4 of the 32-wide message
    int g    = lane >> 3;   // edge slot within warp (0..3)
    int warpId = (blockIdx.x * blockDim.x + threadIdx.x) >> 5;
    int nWarp  = (gridDim.x * blockDim.x) >> 5;

    for (int base = warpId * 4; base < E; base += nWarp * 4) {
        int edge = base + g;
        bool valid = edge < E;
        float es0 = 0.f, es1 = 0.f;
        int sn = 0, dn = 0;
        if (valid) {
            es0 = ef[(size_t)edge * SCH + sub];
            es1 = ef[(size_t)edge * SCH + 8 + sub];
            sn = src[edge];
            dn = dst[edge];
        }
        const float4* zrow = (const float4*)(d_Z + (size_t)sn * ZW) + sub;
        float4 acc = make_float4(0.f, 0.f, 0.f, 0.f);
        #pragma unroll
        for (int s = 0; s < SG; s++) {
            float c;
            if (s < SCH) {
                float v = (s < 8) ? es0 : es1;
                c = __shfl_sync(0xffffffffu, v, (lane & 24) | (s & 7));
            } else {
                c = 1.0f;   // bias slot
            }
            float4 zv = zrow[s * 8];
            acc.x = fmaf(c, zv.x, acc.x);
            acc.y = fmaf(c, zv.y, acc.y);
            acc.z = fmaf(c, zv.z, acc.z);
            acc.w = fmaf(c, zv.w, acc.w);
        }
        if (valid) {
            float* a = d_agg + (size_t)dn * FCH + sub * 4;
            asm volatile("red.global.add.v4.f32 [%0], {%1, %2, %3, %4};"
                         :: "l"(a), "f"(acc.x), "f"(acc.y), "f"(acc.z), "f"(acc.w)
                         : "memory");
        }
    }
}

// ---------------------------------------------------------------------------
// K3: hout[n] = relu(agg[n] + h[n] @ root + bias). do_pool: accumulate
//     sum over nodes into d_pooled instead of storing hout.
// ---------------------------------------------------------------------------
__global__ __launch_bounds__(256) void k_node(
    const float* __restrict__ hin_ext, const float* __restrict__ root,
    const float* __restrict__ bias, int N, int use_dh, int do_pool)
{
    __shared__ float sR[FCH * FCH];
    __shared__ float sB[FCH];
    __shared__ float sPool[FCH];
    for (int i = threadIdx.x; i < FCH * FCH; i += blockDim.x) sR[i] = root[i];
    if (threadIdx.x < FCH) { sB[threadIdx.x] = bias[threadIdx.x]; sPool[threadIdx.x] = 0.f; }
    __syncthreads();

    const float* hin = use_dh ? d_h : hin_ext;
    const float4* sR4 = (const float4*)sR;
    const float4* sB4 = (const float4*)sB;
    int lane = threadIdx.x & 31;

    float pacc[FCH];
    #pragma unroll
    for (int i = 0; i < FCH; i++) pacc[i] = 0.f;

    for (int n = blockIdx.x * blockDim.x + threadIdx.x; n < N;
         n += gridDim.x * blockDim.x) {
        float xr[FCH];
        const float4* hp = (const float4*)(hin + (size_t)n * FCH);
        #pragma unroll
        for (int i = 0; i < FCH / 4; i++) {
            float4 v = hp[i];
            xr[4*i+0] = v.x; xr[4*i+1] = v.y; xr[4*i+2] = v.z; xr[4*i+3] = v.w;
        }
        const float4* ag = (const float4*)(d_agg + (size_t)n * FCH);
        float4* op = (float4*)(d_h + (size_t)n * FCH);
        #pragma unroll
        for (int o4 = 0; o4 < FCH / 4; o4++) {
            float4 a = ag[o4];
            float4 b = sB4[o4];
            float4 acc = make_float4(a.x + b.x, a.y + b.y, a.z + b.z, a.w + b.w);
            #pragma unroll
            for (int k = 0; k < FCH; k++) {
                float4 w = sR4[k * (FCH / 4) + o4];
                acc.x = fmaf(xr[k], w.x, acc.x);
                acc.y = fmaf(xr[k], w.y, acc.y);
                acc.z = fmaf(xr[k], w.z, acc.z);
                acc.w = fmaf(xr[k], w.w, acc.w);
            }
            acc.x = fmaxf(acc.x, 0.f);
            acc.y = fmaxf(acc.y, 0.f);
            acc.z = fmaxf(acc.z, 0.f);
            acc.w = fmaxf(acc.w, 0.f);
            if (do_pool) {
                pacc[4*o4+0] += acc.x; pacc[4*o4+1] += acc.y;
                pacc[4*o4+2] += acc.z; pacc[4*o4+3] += acc.w;
            } else {
                op[o4] = acc;
            }
        }
    }

    if (do_pool) {
        // rotated channel order -> 32 lanes hit 32 distinct banks each step
        #pragma unroll
        for (int j = 0; j < FCH; j++) {
            int o = (lane + j) & 31;
            atomicAdd(&sPool[o], pacc[o]);
        }
        __syncthreads();
        if (threadIdx.x < FCH)
            atomicAdd(&d_pooled[threadIdx.x], sPool[threadIdx.x]);
    }
}

// ---------------------------------------------------------------------------
// Final: out[0] = pooled . dense_w + dense_b
// ---------------------------------------------------------------------------
__global__ void k_final(const float* __restrict__ dw, const float* __restrict__ db,
                        float* __restrict__ out)
{
    int l = threadIdx.x;
    float v = (l < FCH) ? d_pooled[l] * dw[l] : 0.f;
    #pragma unroll
    for (int off = 16; off > 0; off >>= 1)
        v += __shfl_down_sync(0xffffffffu, v, off);
    if (l == 0) out[0] = v + db[0];
}

extern "C" void kernel_launch(void* const* d_in, const int* in_sizes, int n_in,
                              void* d_out, int out_size)
{
    const float* x      = (const float*)d_in[0];
    const float* e      = (const float*)d_in[1];
    const int*   src    = (const int*)d_in[2];
    const int*   dst    = (const int*)d_in[3];
    const float* fgn_w1 = (const float*)d_in[4];
    const float* fgn_b1 = (const float*)d_in[5];
    const float* root1  = (const float*)d_in[6];
    const float* bias1  = (const float*)d_in[7];
    const float* fgn_w2 = (const float*)d_in[8];
    const float* fgn_b2 = (const float*)d_in[9];
    const float* root2  = (const float*)d_in[10];
    const float* bias2  = (const float*)d_in[11];
    const float* dw     = (const float*)d_in[12];
    const float* db     = (const float*)d_in[13];

    int N = in_sizes[0] / FCH;
    int E = in_sizes[2];
    if (N > N_MAX) N = N_MAX;  // scratch bound (dataset: N=50000)

    size_t smemW = (size_t)FCH * ZW * sizeof(float);  // 69632 B > 48K default
    cudaFuncSetAttribute(k_expand, cudaFuncAttributeMaxDynamicSharedMemorySize,
                         (int)smemW);

    const int XB = 296;                     // expand blocks (grid-stride, 8 nodes/warp)
    const int NB = 444;                     // node-kernel blocks (grid-stride)
    const int EB = (E * 8 + 255) / 256;     // 8 threads per edge

    // Layer 1
    k_expand<<<XB, 256, smemW>>>(x, fgn_w1, fgn_b1, N, /*zero_pooled=*/1, /*use_dh=*/0);
    k_edge<<<EB, 256>>>(e, src, dst, E);
    k_node<<<NB, 256>>>(x, root1, bias1, N, /*use_dh=*/0, /*do_pool=*/0);   // -> d_h

    // Layer 2
    k_expand<<<XB, 256, smemW>>>(x, fgn_w2, fgn_b2, N, 0, /*use_dh=*/1);
    k_edge<<<EB, 256>>>(e, src, dst, E);
    k_node<<<NB, 256>>>(x, root2, bias2, N, /*use_dh=*/1, /*do_pool=*/1);   // -> d_pooled

    k_final<<<1, 32>>>(dw, db, (float*)d_out);
}

// round 6
// speedup vs baseline: 1.3668x; 1.1147x over previous
#include <cuda_runtime.h>
#include <cuda_fp16.h>

#define FCH 32    // node feature channels
#define SCH 16    // edge feature channels
#define SG  17    // s-groups incl. bias slot
#define ZW  (SG*FCH)   // 544
#define N_MAX 50048

// Scratch (device globals; no allocation allowed)
__device__ __half d_Z[(size_t)N_MAX * ZW];     // ~54.5 MB: per-node expanded feats (fp16)
__device__ float d_h[(size_t)N_MAX * FCH];     // layer-1 output
__device__ float d_agg[(size_t)N_MAX * FCH];   // scatter accumulator
__device__ float d_pooled[FCH];

// ---- packed f32x2 helpers (Blackwell) --------------------------------------
__device__ __forceinline__ unsigned long long pack2(float v) {
    unsigned long long r;
    asm("mov.b64 %0, {%1, %1};" : "=l"(r) : "f"(v));
    return r;
}
__device__ __forceinline__ unsigned long long fma2(
    unsigned long long a, unsigned long long b, unsigned long long c) {
    unsigned long long d;
    asm("fma.rn.f32x2 %0, %1, %2, %3;" : "=l"(d) : "l"(a), "l"(b), "l"(c));
    return d;
}
__device__ __forceinline__ unsigned int cvt_h2(unsigned long long p) {
    // pack2 floats (lo,hi) -> half2 bits
    float lo, hi;
    asm("mov.b64 {%0, %1}, %2;" : "=f"(lo), "=f"(hi) : "l"(p));
    __half2 h = __floats2half2_rn(lo, hi);
    return *(unsigned int*)&h;
}

// ---------------------------------------------------------------------------
// K1: Z[n, s, o] = sum_f h[n,f] * Wext[f, s*32+o]   (stored fp16)
//     Warp = 8 nodes. lane -> (g = node slot 0..3, sub = o-chunk 0..7).
//     Each lane computes nodes (base+g) and (base+g+4); math in fma.rn.f32x2.
//     Also zeroes the agg rows (and pooled, once).
// ---------------------------------------------------------------------------
__global__ __launch_bounds__(256) void k_expand(
    const float* __restrict__ h_ext, const float* __restrict__ fgn_w,
    const float* __restrict__ fgn_b, int N, int zero_pooled, int use_dh)
{
    extern __shared__ float sW[];  // [FCH][ZW] = 69632 B
    for (int i = threadIdx.x; i < FCH * ZW; i += blockDim.x) {
        int k = i / ZW;
        int j = i - k * ZW;
        int s = j >> 5, o = j & 31;
        sW[i] = (s < SCH) ? fgn_w[s * (FCH * FCH) + k * FCH + o]
                          : fgn_b[k * FCH + o];
    }
    if (zero_pooled && blockIdx.x == 0 && threadIdx.x < FCH)
        d_pooled[threadIdx.x] = 0.0f;
    __syncthreads();

    const float* h = use_dh ? d_h : h_ext;
    const ulonglong2* sWu = (const ulonglong2*)sW;   // 16B units

    int lane = threadIdx.x & 31;
    int g    = lane >> 3;   // node slot within warp (0..3)
    int sub  = lane & 7;    // which o-chunk (4 channels each)
    int warpId = (blockIdx.x * blockDim.x + threadIdx.x) >> 5;
    int nWarp  = (gridDim.x * blockDim.x) >> 5;

    for (int base = warpId * 8; base < N; base += nWarp * 8) {
        int nA = base + g;
        int nB = base + g + 4;
        int rA = nA < N ? nA : N - 1;
        int rB = nB < N ? nB : N - 1;

        float xa[FCH], xb[FCH];
        const float4* pa = (const float4*)(h + (size_t)rA * FCH);
        const float4* pb = (const float4*)(h + (size_t)rB * FCH);
        #pragma unroll
        for (int i = 0; i < FCH / 4; i++) {
            float4 v = pa[i];
            xa[4*i+0] = v.x; xa[4*i+1] = v.y; xa[4*i+2] = v.z; xa[4*i+3] = v.w;
        }
        #pragma unroll
        for (int i = 0; i < FCH / 4; i++) {
            float4 v = pb[i];
            xb[4*i+0] = v.x; xb[4*i+1] = v.y; xb[4*i+2] = v.z; xb[4*i+3] = v.w;
        }

        float4 zv = make_float4(0.f, 0.f, 0.f, 0.f);
        if (nA < N) ((float4*)(d_agg + (size_t)nA * FCH))[sub] = zv;
        if (nB < N) ((float4*)(d_agg + (size_t)nB * FCH))[sub] = zv;

        __half* zAp = d_Z + (size_t)rA * ZW;
        __half* zBp = d_Z + (size_t)rB * ZW;

        #pragma unroll 1
        for (int s = 0; s < SG; s++) {
            const ulonglong2* wp = sWu + s * 8 + sub;
            unsigned long long a0 = 0, a1 = 0, b0 = 0, b1 = 0;
            #pragma unroll
            for (int k = 0; k < FCH; k++) {
                ulonglong2 w = wp[k * (ZW / 4)];        // one LDS.128
                unsigned long long xA2 = pack2(xa[k]);
                unsigned long long xB2 = pack2(xb[k]);
                a0 = fma2(xA2, w.x, a0);
                a1 = fma2(xA2, w.y, a1);
                b0 = fma2(xB2, w.x, b0);
                b1 = fma2(xB2, w.y, b1);
            }
            uint2 ha; ha.x = cvt_h2(a0); ha.y = cvt_h2(a1);   // 4 halves = 8B
            uint2 hb; hb.x = cvt_h2(b0); hb.y = cvt_h2(b1);
            if (nA < N) *(uint2*)(zAp + s * FCH + sub * 4) = ha;
            if (nB < N) *(uint2*)(zBp + s * FCH + sub * 4) = hb;
        }
    }
}

// ---------------------------------------------------------------------------
// K2: per edge: msg[o] = sum_{s<16} e[e,s]*Z[src,s,o] + Z[src,16,o]
//     4 lanes per edge (each lane owns 8 channels via one 16B fp16 load per s),
//     8 edges per warp. Scatter via two red.global.add.v4.f32 per lane.
// ---------------------------------------------------------------------------
__global__ __launch_bounds__(256) void k_edge(
    const float* __restrict__ ef, const int* __restrict__ src,
    const int* __restrict__ dst, int E)
{
    int lane = threadIdx.x & 31;
    int sub  = lane & 3;    // which 8-channel chunk
    int tid  = blockIdx.x * blockDim.x + threadIdx.x;
    int edge = tid >> 2;
    if (edge >= E) return;

    // edge features: lane loads its float4 of the 64B row
    float4 es = ((const float4*)(ef + (size_t)edge * SCH))[sub];
    int sn = src[edge];
    int dn = dst[edge];

    const uint4* zbase = (const uint4*)(d_Z + (size_t)sn * ZW);  // 16B units
    float acc[8];
    #pragma unroll
    for (int i = 0; i < 8; i++) acc[i] = 0.f;

    #pragma unroll
    for (int s = 0; s < SG; s++) {
        float c;
        if (s < SCH) {
            float comp = ((s & 3) == 0) ? es.x : ((s & 3) == 1) ? es.y
                       : ((s & 3) == 2) ? es.z : es.w;
            c = __shfl_sync(0xffffffffu, comp, (lane & 28) | (s >> 2));
        } else {
            c = 1.0f;   // bias slot
        }
        uint4 zv = zbase[s * 4 + sub];   // 8 halves
        float2 p0 = __half22float2(*(const __half2*)&zv.x);
        float2 p1 = __half22float2(*(const __half2*)&zv.y);
        float2 p2 = __half22float2(*(const __half2*)&zv.z);
        float2 p3 = __half22float2(*(const __half2*)&zv.w);
        acc[0] = fmaf(c, p0.x, acc[0]); acc[1] = fmaf(c, p0.y, acc[1]);
        acc[2] = fmaf(c, p1.x, acc[2]); acc[3] = fmaf(c, p1.y, acc[3]);
        acc[4] = fmaf(c, p2.x, acc[4]); acc[5] = fmaf(c, p2.y, acc[5]);
        acc[6] = fmaf(c, p3.x, acc[6]); acc[7] = fmaf(c, p3.y, acc[7]);
    }

    float* a = d_agg + (size_t)dn * FCH + sub * 8;
    asm volatile("red.global.add.v4.f32 [%0], {%1, %2, %3, %4};"
                 :: "l"(a), "f"(acc[0]), "f"(acc[1]), "f"(acc[2]), "f"(acc[3])
                 : "memory");
    asm volatile("red.global.add.v4.f32 [%0], {%1, %2, %3, %4};"
                 :: "l"(a + 4), "f"(acc[4]), "f"(acc[5]), "f"(acc[6]), "f"(acc[7])
                 : "memory");
}

// ---------------------------------------------------------------------------
// K3: hout[n] = relu(agg[n] + h[n] @ root + bias). do_pool: accumulate
//     sum over nodes into d_pooled instead of storing hout.
// ---------------------------------------------------------------------------
__global__ __launch_bounds__(256) void k_node(
    const float* __restrict__ hin_ext, const float* __restrict__ root,
    const float* __restrict__ bias, int N, int use_dh, int do_pool)
{
    __shared__ float sR[FCH * FCH];
    __shared__ float sB[FCH];
    __shared__ float sPool[FCH];
    for (int i = threadIdx.x; i < FCH * FCH; i += blockDim.x) sR[i] = root[i];
    if (threadIdx.x < FCH) { sB[threadIdx.x] = bias[threadIdx.x]; sPool[threadIdx.x] = 0.f; }
    __syncthreads();

    const float* hin = use_dh ? d_h : hin_ext;
    const float4* sR4 = (const float4*)sR;
    const float4* sB4 = (const float4*)sB;
    int lane = threadIdx.x & 31;

    float pacc[FCH];
    #pragma unroll
    for (int i = 0; i < FCH; i++) pacc[i] = 0.f;

    for (int n = blockIdx.x * blockDim.x + threadIdx.x; n < N;
         n += gridDim.x * blockDim.x) {
        float xr[FCH];
        const float4* hp = (const float4*)(hin + (size_t)n * FCH);
        #pragma unroll
        for (int i = 0; i < FCH / 4; i++) {
            float4 v = hp[i];
            xr[4*i+0] = v.x; xr[4*i+1] = v.y; xr[4*i+2] = v.z; xr[4*i+3] = v.w;
        }
        const float4* ag = (const float4*)(d_agg + (size_t)n * FCH);
        float4* op = (float4*)(d_h + (size_t)n * FCH);
        #pragma unroll
        for (int o4 = 0; o4 < FCH / 4; o4++) {
            float4 a = ag[o4];
            float4 b = sB4[o4];
            float4 acc = make_float4(a.x + b.x, a.y + b.y, a.z + b.z, a.w + b.w);
            #pragma unroll
            for (int k = 0; k < FCH; k++) {
                float4 w = sR4[k * (FCH / 4) + o4];
                acc.x = fmaf(xr[k], w.x, acc.x);
                acc.y = fmaf(xr[k], w.y, acc.y);
                acc.z = fmaf(xr[k], w.z, acc.z);
                acc.w = fmaf(xr[k], w.w, acc.w);
            }
            acc.x = fmaxf(acc.x, 0.f);
            acc.y = fmaxf(acc.y, 0.f);
            acc.z = fmaxf(acc.z, 0.f);
            acc.w = fmaxf(acc.w, 0.f);
            if (do_pool) {
                pacc[4*o4+0] += acc.x; pacc[4*o4+1] += acc.y;
                pacc[4*o4+2] += acc.z; pacc[4*o4+3] += acc.w;
            } else {
                op[o4] = acc;
            }
        }
    }

    if (do_pool) {
        #pragma unroll
        for (int j = 0; j < FCH; j++) {
            int o = (lane + j) & 31;
            atomicAdd(&sPool[o], pacc[o]);
        }
        __syncthreads();
        if (threadIdx.x < FCH)
            atomicAdd(&d_pooled[threadIdx.x], sPool[threadIdx.x]);
    }
}

// ---------------------------------------------------------------------------
// Final: out[0] = pooled . dense_w + dense_b
// ---------------------------------------------------------------------------
__global__ void k_final(const float* __restrict__ dw, const float* __restrict__ db,
                        float* __restrict__ out)
{
    int l = threadIdx.x;
    float v = (l < FCH) ? d_pooled[l] * dw[l] : 0.f;
    #pragma unroll
    for (int off = 16; off > 0; off >>= 1)
        v += __shfl_down_sync(0xffffffffu, v, off);
    if (l == 0) out[0] = v + db[0];
}

extern "C" void kernel_launch(void* const* d_in, const int* in_sizes, int n_in,
                              void* d_out, int out_size)
{
    const float* x      = (const float*)d_in[0];
    const float* e      = (const float*)d_in[1];
    const int*   src    = (const int*)d_in[2];
    const int*   dst    = (const int*)d_in[3];
    const float* fgn_w1 = (const float*)d_in[4];
    const float* fgn_b1 = (const float*)d_in[5];
    const float* root1  = (const float*)d_in[6];
    const float* bias1  = (const float*)d_in[7];
    const float* fgn_w2 = (const float*)d_in[8];
    const float* fgn_b2 = (const float*)d_in[9];
    const float* root2  = (const float*)d_in[10];
    const float* bias2  = (const float*)d_in[11];
    const float* dw     = (const float*)d_in[12];
    const float* db     = (const float*)d_in[13];

    int N = in_sizes[0] / FCH;
    int E = in_sizes[2];
    if (N > N_MAX) N = N_MAX;  // scratch bound (dataset: N=50000)

    size_t smemW = (size_t)FCH * ZW * sizeof(float);  // 69632 B
    cudaFuncSetAttribute(k_expand, cudaFuncAttributeMaxDynamicSharedMemorySize,
                         (int)smemW);

    const int XB = 296;                     // expand blocks (grid-stride)
    const int NB = 444;                     // node-kernel blocks (grid-stride)
    const int EB = (E * 4 + 255) / 256;     // 4 threads per edge

    // Layer 1
    k_expand<<<XB, 256, smemW>>>(x, fgn_w1, fgn_b1, N, /*zero_pooled=*/1, /*use_dh=*/0);
    k_edge<<<EB, 256>>>(e, src, dst, E);
    k_node<<<NB, 256>>>(x, root1, bias1, N, /*use_dh=*/0, /*do_pool=*/0);   // -> d_h

    // Layer 2
    k_expand<<<XB, 256, smemW>>>(x, fgn_w2, fgn_b2, N, 0, /*use_dh=*/1);
    k_edge<<<EB, 256>>>(e, src, dst, E);
    k_node<<<NB, 256>>>(x, root2, bias2, N, /*use_dh=*/1, /*do_pool=*/1);   // -> d_pooled

    k_final<<<1, 32>>>(dw, db, (float*)d_out);
}

// round 7
// speedup vs baseline: 1.3728x; 1.0044x over previous
#include <cuda_runtime.h>
#include <cuda_fp16.h>

#define FCH 32    // node feature channels
#define SCH 16    // edge feature channels
#define SG  17    // s-groups incl. bias slot
#define ZW  (SG*FCH)   // 544
#define N_MAX 50048

// Scratch (device globals; no allocation allowed)
__device__ __half d_Z[(size_t)N_MAX * ZW];     // ~54.5 MB: per-node expanded feats (fp16)
__device__ float d_h[(size_t)N_MAX * FCH];     // layer-1 output
__device__ float d_agg[(size_t)N_MAX * FCH];   // scatter accumulator
__device__ float d_pooled[FCH];

// ---- packed f32x2 helpers (Blackwell) --------------------------------------
__device__ __forceinline__ unsigned long long pack2(float v) {
    unsigned long long r;
    asm("mov.b64 %0, {%1, %1};" : "=l"(r) : "f"(v));
    return r;
}
__device__ __forceinline__ unsigned long long fma2(
    unsigned long long a, unsigned long long b, unsigned long long c) {
    unsigned long long d;
    asm("fma.rn.f32x2 %0, %1, %2, %3;" : "=l"(d) : "l"(a), "l"(b), "l"(c));
    return d;
}
__device__ __forceinline__ unsigned int cvt_h2(unsigned long long p) {
    // pack2 floats (lo,hi) -> half2 bits
    float lo, hi;
    asm("mov.b64 {%0, %1}, %2;" : "=f"(lo), "=f"(hi) : "l"(p));
    __half2 h = __floats2half2_rn(lo, hi);
    return *(unsigned int*)&h;
}

// ---------------------------------------------------------------------------
// K1: Z[n, s, o] = sum_f h[n,f] * Wext[f, s*32+o]   (stored fp16)
//     Warp = 8 nodes. lane -> (g = node slot 0..3, sub = o-chunk 0..7).
//     Each lane computes nodes (base+g) and (base+g+4); math in fma.rn.f32x2.
//     Also zeroes the agg rows (and pooled, once).
// ---------------------------------------------------------------------------
__global__ __launch_bounds__(256) void k_expand(
    const float* __restrict__ h_ext, const float* __restrict__ fgn_w,
    const float* __restrict__ fgn_b, int N, int zero_pooled, int use_dh)
{
    extern __shared__ float sW[];  // [FCH][ZW] = 69632 B
    for (int i = threadIdx.x; i < FCH * ZW; i += blockDim.x) {
        int k = i / ZW;
        int j = i - k * ZW;
        int s = j >> 5, o = j & 31;
        sW[i] = (s < SCH) ? fgn_w[s * (FCH * FCH) + k * FCH + o]
                          : fgn_b[k * FCH + o];
    }
    if (zero_pooled && blockIdx.x == 0 && threadIdx.x < FCH)
        d_pooled[threadIdx.x] = 0.0f;
    __syncthreads();

    const float* h = use_dh ? d_h : h_ext;
    const ulonglong2* sWu = (const ulonglong2*)sW;   // 16B units

    int lane = threadIdx.x & 31;
    int g    = lane >> 3;   // node slot within warp (0..3)
    int sub  = lane & 7;    // which o-chunk (4 channels each)
    int warpId = (blockIdx.x * blockDim.x + threadIdx.x) >> 5;
    int nWarp  = (gridDim.x * blockDim.x) >> 5;

    for (int base = warpId * 8; base < N; base += nWarp * 8) {
        int nA = base + g;
        int nB = base + g + 4;
        int rA = nA < N ? nA : N - 1;
        int rB = nB < N ? nB : N - 1;

        float xa[FCH], xb[FCH];
        const float4* pa = (const float4*)(h + (size_t)rA * FCH);
        const float4* pb = (const float4*)(h + (size_t)rB * FCH);
        #pragma unroll
        for (int i = 0; i < FCH / 4; i++) {
            float4 v = pa[i];
            xa[4*i+0] = v.x; xa[4*i+1] = v.y; xa[4*i+2] = v.z; xa[4*i+3] = v.w;
        }
        #pragma unroll
        for (int i = 0; i < FCH / 4; i++) {
            float4 v = pb[i];
            xb[4*i+0] = v.x; xb[4*i+1] = v.y; xb[4*i+2] = v.z; xb[4*i+3] = v.w;
        }

        float4 zv = make_float4(0.f, 0.f, 0.f, 0.f);
        if (nA < N) ((float4*)(d_agg + (size_t)nA * FCH))[sub] = zv;
        if (nB < N) ((float4*)(d_agg + (size_t)nB * FCH))[sub] = zv;

        __half* zAp = d_Z + (size_t)rA * ZW;
        __half* zBp = d_Z + (size_t)rB * ZW;

        #pragma unroll 1
        for (int s = 0; s < SG; s++) {
            const ulonglong2* wp = sWu + s * 8 + sub;
            unsigned long long a0 = 0, a1 = 0, b0 = 0, b1 = 0;
            #pragma unroll
            for (int k = 0; k < FCH; k++) {
                ulonglong2 w = wp[k * (ZW / 4)];        // one LDS.128
                unsigned long long xA2 = pack2(xa[k]);
                unsigned long long xB2 = pack2(xb[k]);
                a0 = fma2(xA2, w.x, a0);
                a1 = fma2(xA2, w.y, a1);
                b0 = fma2(xB2, w.x, b0);
                b1 = fma2(xB2, w.y, b1);
            }
            uint2 ha; ha.x = cvt_h2(a0); ha.y = cvt_h2(a1);   // 4 halves = 8B
            uint2 hb; hb.x = cvt_h2(b0); hb.y = cvt_h2(b1);
            if (nA < N) *(uint2*)(zAp + s * FCH + sub * 4) = ha;
            if (nB < N) *(uint2*)(zBp + s * FCH + sub * 4) = hb;
        }
    }
}

// ---------------------------------------------------------------------------
// K2: per edge: msg[o] = sum_{s<16} e[e,s]*Z[src,s,o] + Z[src,16,o]
//     4 lanes per edge (each lane owns 8 channels via one 16B fp16 load per s),
//     8 edges per warp. Math in HFMA2 (fp16 accumulate); only the final 8
//     values are converted to fp32 for the red.global.add.v4 scatter.
// ---------------------------------------------------------------------------
__global__ __launch_bounds__(256) void k_edge(
    const float* __restrict__ ef, const int* __restrict__ src,
    const int* __restrict__ dst, int E)
{
    int lane = threadIdx.x & 31;
    int sub  = lane & 3;    // which 8-channel chunk
    int tid  = blockIdx.x * blockDim.x + threadIdx.x;
    int edge = tid >> 2;
    if (edge >= E) return;

    // edge features: lane loads its float4 of the 64B row
    float4 es = ((const float4*)(ef + (size_t)edge * SCH))[sub];
    int sn = src[edge];
    int dn = dst[edge];

    const uint4* zbase = (const uint4*)(d_Z + (size_t)sn * ZW);  // 16B units

    // init accumulators from bias slot (s=16, coefficient 1)
    uint4 zb = zbase[16 * 4 + sub];
    __half2 acc0 = *(const __half2*)&zb.x;
    __half2 acc1 = *(const __half2*)&zb.y;
    __half2 acc2 = *(const __half2*)&zb.z;
    __half2 acc3 = *(const __half2*)&zb.w;

    #pragma unroll
    for (int s = 0; s < SCH; s++) {
        float comp = ((s & 3) == 0) ? es.x : ((s & 3) == 1) ? es.y
                   : ((s & 3) == 2) ? es.z : es.w;
        float c = __shfl_sync(0xffffffffu, comp, (lane & 28) | (s >> 2));
        __half2 c2 = __float2half2_rn(c);
        uint4 zv = zbase[s * 4 + sub];   // 8 halves
        acc0 = __hfma2(c2, *(const __half2*)&zv.x, acc0);
        acc1 = __hfma2(c2, *(const __half2*)&zv.y, acc1);
        acc2 = __hfma2(c2, *(const __half2*)&zv.z, acc2);
        acc3 = __hfma2(c2, *(const __half2*)&zv.w, acc3);
    }

    float2 f0 = __half22float2(acc0);
    float2 f1 = __half22float2(acc1);
    float2 f2 = __half22float2(acc2);
    float2 f3 = __half22float2(acc3);

    float* a = d_agg + (size_t)dn * FCH + sub * 8;
    asm volatile("red.global.add.v4.f32 [%0], {%1, %2, %3, %4};"
                 :: "l"(a), "f"(f0.x), "f"(f0.y), "f"(f1.x), "f"(f1.y)
                 : "memory");
    asm volatile("red.global.add.v4.f32 [%0], {%1, %2, %3, %4};"
                 :: "l"(a + 4), "f"(f2.x), "f"(f2.y), "f"(f3.x), "f"(f3.y)
                 : "memory");
}

// ---------------------------------------------------------------------------
// K3: hout[n] = relu(agg[n] + h[n] @ root + bias). do_pool: accumulate
//     sum over nodes into d_pooled instead of storing hout.
// ---------------------------------------------------------------------------
__global__ __launch_bounds__(256) void k_node(
    const float* __restrict__ hin_ext, const float* __restrict__ root,
    const float* __restrict__ bias, int N, int use_dh, int do_pool)
{
    __shared__ float sR[FCH * FCH];
    __shared__ float sB[FCH];
    __shared__ float sPool[FCH];
    for (int i = threadIdx.x; i < FCH * FCH; i += blockDim.x) sR[i] = root[i];
    if (threadIdx.x < FCH) { sB[threadIdx.x] = bias[threadIdx.x]; sPool[threadIdx.x] = 0.f; }
    __syncthreads();

    const float* hin = use_dh ? d_h : hin_ext;
    const float4* sR4 = (const float4*)sR;
    const float4* sB4 = (const float4*)sB;
    int lane = threadIdx.x & 31;

    float pacc[FCH];
    #pragma unroll
    for (int i = 0; i < FCH; i++) pacc[i] = 0.f;

    for (int n = blockIdx.x * blockDim.x + threadIdx.x; n < N;
         n += gridDim.x * blockDim.x) {
        float xr[FCH];
        const float4* hp = (const float4*)(hin + (size_t)n * FCH);
        #pragma unroll
        for (int i = 0; i < FCH / 4; i++) {
            float4 v = hp[i];
            xr[4*i+0] = v.x; xr[4*i+1] = v.y; xr[4*i+2] = v.z; xr[4*i+3] = v.w;
        }
        const float4* ag = (const float4*)(d_agg + (size_t)n * FCH);
        float4* op = (float4*)(d_h + (size_t)n * FCH);
        #pragma unroll
        for (int o4 = 0; o4 < FCH / 4; o4++) {
            float4 a = ag[o4];
            float4 b = sB4[o4];
            float4 acc = make_float4(a.x + b.x, a.y + b.y, a.z + b.z, a.w + b.w);
            #pragma unroll
            for (int k = 0; k < FCH; k++) {
                float4 w = sR4[k * (FCH / 4) + o4];
                acc.x = fmaf(xr[k], w.x, acc.x);
                acc.y = fmaf(xr[k], w.y, acc.y);
                acc.z = fmaf(xr[k], w.z, acc.z);
                acc.w = fmaf(xr[k], w.w, acc.w);
            }
            acc.x = fmaxf(acc.x, 0.f);
            acc.y = fmaxf(acc.y, 0.f);
            acc.z = fmaxf(acc.z, 0.f);
            acc.w = fmaxf(acc.w, 0.f);
            if (do_pool) {
                pacc[4*o4+0] += acc.x; pacc[4*o4+1] += acc.y;
                pacc[4*o4+2] += acc.z; pacc[4*o4+3] += acc.w;
            } else {
                op[o4] = acc;
            }
        }
    }

    if (do_pool) {
        #pragma unroll
        for (int j = 0; j < FCH; j++) {
            int o = (lane + j) & 31;
            atomicAdd(&sPool[o], pacc[o]);
        }
        __syncthreads();
        if (threadIdx.x < FCH)
            atomicAdd(&d_pooled[threadIdx.x], sPool[threadIdx.x]);
    }
}

// ---------------------------------------------------------------------------
// Final: out[0] = pooled . dense_w + dense_b
// ---------------------------------------------------------------------------
__global__ void k_final(const float* __restrict__ dw, const float* __restrict__ db,
                        float* __restrict__ out)
{
    int l = threadIdx.x;
    float v = (l < FCH) ? d_pooled[l] * dw[l] : 0.f;
    #pragma unroll
    for (int off = 16; off > 0; off >>= 1)
        v += __shfl_down_sync(0xffffffffu, v, off);
    if (l == 0) out[0] = v + db[0];
}

extern "C" void kernel_launch(void* const* d_in, const int* in_sizes, int n_in,
                              void* d_out, int out_size)
{
    const float* x      = (const float*)d_in[0];
    const float* e      = (const float*)d_in[1];
    const int*   src    = (const int*)d_in[2];
    const int*   dst    = (const int*)d_in[3];
    const float* fgn_w1 = (const float*)d_in[4];
    const float* fgn_b1 = (const float*)d_in[5];
    const float* root1  = (const float*)d_in[6];
    const float* bias1  = (const float*)d_in[7];
    const float* fgn_w2 = (const float*)d_in[8];
    const float* fgn_b2 = (const float*)d_in[9];
    const float* root2  = (const float*)d_in[10];
    const float* bias2  = (const float*)d_in[11];
    const float* dw     = (const float*)d_in[12];
    const float* db     = (const float*)d_in[13];

    int N = in_sizes[0] / FCH;
    int E = in_sizes[2];
    if (N > N_MAX) N = N_MAX;  // scratch bound (dataset: N=50000)

    size_t smemW = (size_t)FCH * ZW * sizeof(float);  // 69632 B
    cudaFuncSetAttribute(k_expand, cudaFuncAttributeMaxDynamicSharedMemorySize,
                         (int)smemW);

    const int XB = 296;                     // expand blocks (grid-stride)
    const int NB = 444;                     // node-kernel blocks (grid-stride)
    const int EB = (E * 4 + 255) / 256;     // 4 threads per edge

    // Layer 1
    k_expand<<<XB, 256, smemW>>>(x, fgn_w1, fgn_b1, N, /*zero_pooled=*/1, /*use_dh=*/0);
    k_edge<<<EB, 256>>>(e, src, dst, E);
    k_node<<<NB, 256>>>(x, root1, bias1, N, /*use_dh=*/0, /*do_pool=*/0);   // -> d_h

    // Layer 2
    k_expand<<<XB, 256, smemW>>>(x, fgn_w2, fgn_b2, N, 0, /*use_dh=*/1);
    k_edge<<<EB, 256>>>(e, src, dst, E);
    k_node<<<NB, 256>>>(x, root2, bias2, N, /*use_dh=*/1, /*do_pool=*/1);   // -> d_pooled

    k_final<<<1, 32>>>(dw, db, (float*)d_out);
}